// round 2
// baseline (speedup 1.0000x reference)
#include <cuda_runtime.h>

// LMorph: out[n,o,h,w] = sum_{c,ij} t^(p+1) / sum_{c,ij} t^p,
//   t = (1 + (in - gmin)/(gmax - gmin))[n,c,h+i,w+j] + filt[o,c,i,j]
// Shapes: in [4,2,256,256] f32, filt [4,2,5,5] f32, p [4,2] f32, out [4,4,252,252] f32.

#define N_  4
#define C_  2
#define O_  4
#define H_  256
#define W_  256
#define KH_ 5
#define KW_ 5
#define HO_ 252
#define WO_ 252

#define TX 32
#define TY 8
#define SW (TX + KW_ - 1)   // 36
#define SH (TY + KH_ - 1)   // 12

__device__ __forceinline__ float fast_lg2(float x) {
    float r;
    asm("lg2.approx.f32 %0, %1;" : "=f"(r) : "f"(x));
    return r;
}
__device__ __forceinline__ float fast_ex2(float x) {
    float r;
    asm("ex2.approx.f32 %0, %1;" : "=f"(r) : "f"(x));
    return r;
}

// ---- global min/max scratch (device globals: no allocations allowed) ----
__device__ unsigned g_lo_key;   // orderable-uint encoding of min
__device__ unsigned g_hi_key;   // orderable-uint encoding of max

__device__ __forceinline__ unsigned f2key(float f) {
    unsigned u = __float_as_uint(f);
    return (u & 0x80000000u) ? ~u : (u | 0x80000000u);
}
__device__ __forceinline__ float key2f(unsigned k) {
    unsigned u = (k & 0x80000000u) ? (k & 0x7FFFFFFFu) : ~k;
    return __uint_as_float(u);
}

__global__ void lmorph_init_kernel() {
    g_lo_key = 0xFFFFFFFFu;
    g_hi_key = 0u;
}

__global__ void lmorph_minmax_kernel(const float* __restrict__ in, int n4) {
    unsigned lo = 0xFFFFFFFFu, hi = 0u;
    const float4* in4 = (const float4*)in;
    for (int i = blockIdx.x * blockDim.x + threadIdx.x; i < n4;
         i += gridDim.x * blockDim.x) {
        float4 v = in4[i];
        unsigned kx = f2key(v.x), ky = f2key(v.y), kz = f2key(v.z), kw = f2key(v.w);
        hi = max(hi, max(max(kx, ky), max(kz, kw)));
        lo = min(lo, min(min(kx, ky), min(kz, kw)));
    }
#pragma unroll
    for (int s = 16; s > 0; s >>= 1) {
        hi = max(hi, __shfl_xor_sync(0xFFFFFFFFu, hi, s));
        lo = min(lo, __shfl_xor_sync(0xFFFFFFFFu, lo, s));
    }
    if ((threadIdx.x & 31) == 0) {
        atomicMax(&g_hi_key, hi);
        atomicMin(&g_lo_key, lo);
    }
}

__global__ __launch_bounds__(TX * TY) void lmorph_main_kernel(
    const float* __restrict__ in,
    const float* __restrict__ filt,
    const float* __restrict__ p,
    float* __restrict__ out)
{
    __shared__ float sx[C_][SH][SW];
    __shared__ float sf[C_][KH_ * KW_];
    __shared__ float spe[C_];

    const int z = blockIdx.z;          // n*O_ + o
    const int n = z >> 2;
    const int o = z & 3;
    const int w0 = blockIdx.x * TX;
    const int h0 = blockIdx.y * TY;
    const int tid = threadIdx.x;
    const int tx = tid & 31;
    const int ty = tid >> 5;

    const float lo = key2f(g_lo_key);
    const float hi = key2f(g_hi_key);
    const float inv = __fdividef(1.0f, hi - lo);

    if (tid < C_ * KH_ * KW_) {
        int c = tid / (KH_ * KW_);
        int k = tid % (KH_ * KW_);
        sf[c][k] = filt[(o * C_ + c) * (KH_ * KW_) + k];
    }
    if (tid < C_) spe[tid] = p[o * C_ + tid];

    // cooperative load of the 2-channel input tile (rescaled to [1,2])
    for (int idx = tid; idx < C_ * SH * SW; idx += TX * TY) {
        int c   = idx / (SH * SW);
        int r   = (idx / SW) % SH;
        int col = idx % SW;
        int h = h0 + r, w = w0 + col;
        float v = lo;  // OOB filler -> x = 1, always safe for pow
        if (h < H_ && w < W_)
            v = in[((n * C_ + c) * H_ + h) * W_ + w];
        sx[c][r][col] = 1.0f + (v - lo) * inv;
    }
    __syncthreads();

    const int oh = h0 + ty;
    const int ow = w0 + tx;
    if (oh >= HO_ || ow >= WO_) return;

    float num0 = 0.f, den0 = 0.f, num1 = 0.f, den1 = 0.f;
#pragma unroll
    for (int c = 0; c < C_; c++) {
        const float pe = spe[c];
#pragma unroll
        for (int i = 0; i < KH_; i++) {
#pragma unroll
            for (int j = 0; j < KW_; j++) {
                float t = sx[c][ty + i][tx + j] + sf[c][i * KW_ + j];
                float w = fast_ex2(pe * fast_lg2(t));   // t^pe, 2x MUFU
                if (((i * KW_ + j) & 1) == 0) {
                    den0 += w;
                    num0 = fmaf(w, t, num0);
                } else {
                    den1 += w;
                    num1 = fmaf(w, t, num1);
                }
            }
        }
    }
    out[((n * O_ + o) * HO_ + oh) * WO_ + ow] =
        __fdividef(num0 + num1, den0 + den1);
}

extern "C" void kernel_launch(void* const* d_in, const int* in_sizes, int n_in,
                              void* d_out, int out_size) {
    const float* in   = (const float*)d_in[0];   // [4,2,256,256]
    const float* filt = (const float*)d_in[1];   // [4,2,5,5]
    const float* p    = (const float*)d_in[2];   // [4,2]
    float* out = (float*)d_out;                  // [4,4,252,252]

    lmorph_init_kernel<<<1, 1>>>();
    lmorph_minmax_kernel<<<128, 256>>>(in, (N_ * C_ * H_ * W_) / 4);

    dim3 block(TX * TY);
    dim3 grid((WO_ + TX - 1) / TX, (HO_ + TY - 1) / TY, N_ * O_);
    lmorph_main_kernel<<<grid, block>>>(in, filt, p, out);
}